// round 14
// baseline (speedup 1.0000x reference)
#include <cuda_runtime.h>

#define TPB    128
#define QPT    8             // queries per thread
#define QPB    (TPB*QPT)     // 1024 queries per block
#define PAIRS  256           // candidate pairs per tile (512 candidates)
#define BX0    8             // 8192/1024  query-blocks dir0
#define BY0    64            // 32768/512  tiles dir0
#define BX1    32            // 32768/1024 query-blocks dir1
#define BY1    16            // 8192/512   tiles dir1
#define NB0    (BX0*BY0)     // 512
#define NB1    (BX1*BY1)     // 512
#define RLB    512           // resolve_loss blocks

// ---------------- static scratch (no allocations) ----------------------------
__device__ float4             g_gxy[16384];   // gt  pairs: (x0,x1,y0,y1)
__device__ float4             g_gzw[16384];   // gt  pairs: (z0,z1,w0,w1)
__device__ float4             g_pxy[4096];    // pred pairs
__device__ float4             g_pzw[4096];
__device__ unsigned long long g_best1[8192];  // per pred: key | tile
__device__ unsigned long long g_best2[32768]; // per gt:   key | tile
__device__ float              g_partial[2*RLB];
__device__ unsigned           g_done;

// ---------------- packed f32x2 helpers ---------------------------------------
__device__ __forceinline__ unsigned long long splat2(float f) {
    unsigned long long r;
    asm("mov.b64 %0, {%1, %1};" : "=l"(r) : "f"(f));
    return r;
}
__device__ __forceinline__ unsigned long long ffma2(unsigned long long a,
                                                    unsigned long long b,
                                                    unsigned long long c) {
    unsigned long long d;
    asm("fma.rn.f32x2 %0, %1, %2, %3;" : "=l"(d) : "l"(a), "l"(b), "l"(c));
    return d;
}
__device__ __forceinline__ void unpack2(unsigned long long v, float& lo, float& hi) {
    asm("mov.b64 {%0, %1}, %2;" : "=f"(lo), "=f"(hi) : "l"(v));
}
// monotone float -> sortable unsigned, and exact inverse
__device__ __forceinline__ unsigned fkey(float f) {
    unsigned u = __float_as_uint(f);
    return u ^ ((unsigned)((int)u >> 31) | 0x80000000u);
}
__device__ __forceinline__ float unfkey(unsigned k) {
    return __uint_as_float((k & 0x80000000u) ? (k ^ 0x80000000u) : ~k);
}

// ---------------- prep: init winners + pack paired-SoA (one kernel) ----------
__global__ void prep_kernel(const float* __restrict__ pp,
                            const float* __restrict__ gp, int N, int M) {
    int i = blockIdx.x * blockDim.x + threadIdx.x;
    if (i == 0) g_done = 0;
    if (i < N) g_best1[i] = ~0ULL;
    if (i < M) g_best2[i] = ~0ULL;
    if (i < N / 2) {
        float x0 = pp[6*i],   y0 = pp[6*i+1], z0 = pp[6*i+2];
        float x1 = pp[6*i+3], y1 = pp[6*i+4], z1 = pp[6*i+5];
        g_pxy[i] = make_float4(x0, x1, y0, y1);
        g_pzw[i] = make_float4(z0, z1, x0*x0 + y0*y0 + z0*z0,
                                       x1*x1 + y1*y1 + z1*z1);
    }
    if (i < M / 2) {
        float x0 = gp[6*i],   y0 = gp[6*i+1], z0 = gp[6*i+2];
        float x1 = gp[6*i+3], y1 = gp[6*i+4], z1 = gp[6*i+5];
        g_gxy[i] = make_float4(x0, x1, y0, y1);
        g_gzw[i] = make_float4(z0, z1, x0*x0 + y0*y0 + z0*z0,
                                       x1*x1 + y1*y1 + z1*z1);
    }
}

// ---------------- main: both directions, pure-min tiles ----------------------
// score(q, c) = |c|^2 - 2 q.c  (identical chain to validated rounds)
// atomicMin payload = (fkey(min)<<32 | tileId): smallest score, then earliest
// tile -> the tile holding the global first occurrence.
__global__ __launch_bounds__(TPB) void nn_main(const float* __restrict__ pp,
                                               const float* __restrict__ gp) {
    __shared__ ulonglong2 sxy[PAIRS];
    __shared__ ulonglong2 szw[PAIRS];

    int b = blockIdx.x;
    const ulonglong2 *gxy, *gzw;
    const float* qp;
    unsigned long long* best;
    int bx, by;
    if (b < NB0) {               // dir 0: pred queries vs gt candidates
        bx = b % BX0; by = b / BX0;
        gxy = (const ulonglong2*)g_gxy; gzw = (const ulonglong2*)g_gzw;
        qp = pp; best = g_best1;
    } else {                     // dir 1: gt queries vs pred candidates
        b -= NB0;
        bx = b % BX1; by = b / BX1;
        gxy = (const ulonglong2*)g_pxy; gzw = (const ulonglong2*)g_pzw;
        qp = gp; best = g_best2;
    }

    const int pairbase = by * PAIRS;
    for (int t = threadIdx.x; t < PAIRS; t += TPB) {
        sxy[t] = gxy[pairbase + t];
        szw[t] = gzw[pairbase + t];
    }
    __syncthreads();

    int q[QPT];
    unsigned long long Qx[QPT], Qy[QPT], Qz[QPT];
#pragma unroll
    for (int k = 0; k < QPT; k++) {
        q[k]  = bx * QPB + k * TPB + threadIdx.x;
        Qx[k] = splat2(-2.0f * qp[3*q[k]]);
        Qy[k] = splat2(-2.0f * qp[3*q[k]+1]);
        Qz[k] = splat2(-2.0f * qp[3*q[k]+2]);
    }

    float bm0[QPT], bm1[QPT];
#pragma unroll
    for (int k = 0; k < QPT; k++) { bm0[k] = 3.4e38f; bm1[k] = 3.4e38f; }

#pragma unroll 4
    for (int t = 0; t < PAIRS; t++) {
        ulonglong2 a = sxy[t];
        ulonglong2 c = szw[t];
#pragma unroll
        for (int k = 0; k < QPT; k++) {
            unsigned long long s =
                ffma2(Qx[k], a.x, ffma2(Qy[k], a.y, ffma2(Qz[k], c.x, c.y)));
            float s0, s1; unpack2(s, s0, s1);
            bm0[k] = fminf(bm0[k], s0);
            bm1[k] = fminf(bm1[k], s1);
        }
    }

#pragma unroll
    for (int k = 0; k < QPT; k++) {
        float bm = fminf(bm0[k], bm1[k]);
        atomicMin(&best[q[k]],
                  ((unsigned long long)fkey(bm) << 32) | (unsigned)by);
    }
}

// ---------------- resolve + loss + final reduce (last-block) -----------------
// Rescans each query's winning tile with bit-identical arithmetic, takes the
// smallest exactly-equal index, accumulates normal dots, and the last block to
// finish performs the deterministic final reduction and writes the output.
__global__ __launch_bounds__(256) void resolve_loss(const float* __restrict__ pp,
                                                    const float* __restrict__ gp,
                                                    const float* __restrict__ pn,
                                                    const float* __restrict__ gn,
                                                    float* __restrict__ out,
                                                    int N, int M) {
    const int wid  = threadIdx.x >> 5;
    const int lane = threadIdx.x & 31;
    const int warp = blockIdx.x * 8 + wid;
    const int nw   = RLB * 8;
    float s1 = 0.f, s2 = 0.f;

    for (int w = warp; w < N + M; w += nw) {
        int dir = (w >= N);
        int q   = dir ? (w - N) : w;
        unsigned long long bk = dir ? g_best2[q] : g_best1[q];
        float bm = unfkey((unsigned)(bk >> 32));
        int tile = (int)(unsigned)bk;

        const ulonglong2* gxy = dir ? (const ulonglong2*)g_pxy
                                    : (const ulonglong2*)g_gxy;
        const ulonglong2* gzw = dir ? (const ulonglong2*)g_pzw
                                    : (const ulonglong2*)g_gzw;
        const float* qp = dir ? gp : pp;

        unsigned long long Qx = splat2(-2.0f * qp[3*q]);
        unsigned long long Qy = splat2(-2.0f * qp[3*q+1]);
        unsigned long long Qz = splat2(-2.0f * qp[3*q+2]);

        const int base = tile * PAIRS;
        int idx = 0x7FFFFFFF;
#pragma unroll
        for (int t = lane; t < PAIRS; t += 32) {
            ulonglong2 a = gxy[base + t];
            ulonglong2 c = gzw[base + t];
            unsigned long long s =
                ffma2(Qx, a.x, ffma2(Qy, a.y, ffma2(Qz, c.x, c.y)));
            float s0, sh; unpack2(s, s0, sh);
            if (sh == bm) idx = min(idx, 2*(base + t) + 1);
            if (s0 == bm) idx = min(idx, 2*(base + t));
        }
#pragma unroll
        for (int o = 16; o; o >>= 1)
            idx = min(idx, __shfl_xor_sync(0xFFFFFFFFu, idx, o));

        if (lane == 0) {
            const float* qn = dir ? gn : pn;   // query-side normals
            const float* cn = dir ? pn : gn;   // candidate-side normals
            float d = qn[3*q] * cn[3*idx] + qn[3*q+1] * cn[3*idx+1]
                    + qn[3*q+2] * cn[3*idx+2];
            if (dir) s2 += d; else s1 += d;
        }
    }

    __shared__ float sh1[8], sh2[8];
    if (lane == 0) { sh1[wid] = s1; sh2[wid] = s2; }
    __syncthreads();
    if (threadIdx.x == 0) {
        float a = 0.f, b = 0.f;
#pragma unroll
        for (int k = 0; k < 8; k++) { a += sh1[k]; b += sh2[k]; }
        g_partial[blockIdx.x]       = a;
        g_partial[RLB + blockIdx.x] = b;
    }

    // ---- last block performs the final deterministic reduction ----
    __shared__ bool amLast;
    __threadfence();
    if (threadIdx.x == 0)
        amLast = (atomicAdd(&g_done, 1u) == RLB - 1);
    __syncthreads();
    if (amLast) {
        __shared__ float sa[256], sb[256];
        int t = threadIdx.x;
        sa[t] = g_partial[t]       + g_partial[256 + t];
        sb[t] = g_partial[512 + t] + g_partial[768 + t];
        __syncthreads();
        for (int o = 128; o > 0; o >>= 1) {
            if (t < o) { sa[t] += sa[t + o]; sb[t] += sb[t + o]; }
            __syncthreads();
        }
        if (t == 0)
            out[0] = 2.0f - sa[0] / (float)N - sb[0] / (float)M;
    }
}

// ---------------- launch (3 nodes) -------------------------------------------
extern "C" void kernel_launch(void* const* d_in, const int* in_sizes, int n_in,
                              void* d_out, int out_size) {
    const float* pred_pts = (const float*)d_in[0];
    const float* pred_nrm = (const float*)d_in[1];
    const float* gt_pts   = (const float*)d_in[2];
    const float* gt_nrm   = (const float*)d_in[3];
    float* out = (float*)d_out;

    const int N = in_sizes[0] / 3;   // 8192
    const int M = in_sizes[2] / 3;   // 32768

    prep_kernel<<<(M + 255) / 256, 256>>>(pred_pts, gt_pts, N, M);
    nn_main<<<NB0 + NB1, TPB>>>(pred_pts, gt_pts);       // 1024 blocks
    resolve_loss<<<RLB, 256>>>(pred_pts, gt_pts, pred_nrm, gt_nrm, out, N, M);
}

// round 15
// speedup vs baseline: 1.0148x; 1.0148x over previous
#include <cuda_runtime.h>

#define TPB    128
#define QPT    4             // queries per thread
#define QPB    (TPB*QPT)     // 512 queries per block
#define PAIRS  256           // candidate pairs per tile (512 candidates)
#define BX0    16            // 8192/512   query-blocks dir0
#define BY0    64            // 32768/512  tiles dir0
#define BX1    64            // 32768/512  query-blocks dir1
#define BY1    16            // 8192/512   tiles dir1
#define NB0    (BX0*BY0)     // 1024
#define NB1    (BX1*BY1)     // 1024
#define RLB    512           // resolve_loss blocks

// ---------------- static scratch (no allocations) ----------------------------
__device__ float4             g_gxy[16384];   // gt  pairs: (x0,x1,y0,y1)
__device__ float4             g_gzw[16384];   // gt  pairs: (z0,z1,w0,w1)
__device__ float4             g_pxy[4096];    // pred pairs
__device__ float4             g_pzw[4096];
__device__ unsigned long long g_best1[8192];  // per pred: key | tile
__device__ unsigned long long g_best2[32768]; // per gt:   key | tile
__device__ float              g_partial[2*RLB];
__device__ unsigned           g_done;

// ---------------- packed f32x2 helpers ---------------------------------------
__device__ __forceinline__ unsigned long long splat2(float f) {
    unsigned long long r;
    asm("mov.b64 %0, {%1, %1};" : "=l"(r) : "f"(f));
    return r;
}
__device__ __forceinline__ unsigned long long ffma2(unsigned long long a,
                                                    unsigned long long b,
                                                    unsigned long long c) {
    unsigned long long d;
    asm("fma.rn.f32x2 %0, %1, %2, %3;" : "=l"(d) : "l"(a), "l"(b), "l"(c));
    return d;
}
__device__ __forceinline__ void unpack2(unsigned long long v, float& lo, float& hi) {
    asm("mov.b64 {%0, %1}, %2;" : "=f"(lo), "=f"(hi) : "l"(v));
}
// monotone float -> sortable unsigned, and exact inverse
__device__ __forceinline__ unsigned fkey(float f) {
    unsigned u = __float_as_uint(f);
    return u ^ ((unsigned)((int)u >> 31) | 0x80000000u);
}
__device__ __forceinline__ float unfkey(unsigned k) {
    return __uint_as_float((k & 0x80000000u) ? (k ^ 0x80000000u) : ~k);
}

// ---------------- prep: init winners + pack paired-SoA (one kernel) ----------
__global__ void prep_kernel(const float* __restrict__ pp,
                            const float* __restrict__ gp, int N, int M) {
    int i = blockIdx.x * blockDim.x + threadIdx.x;
    if (i == 0) g_done = 0;
    if (i < N) g_best1[i] = ~0ULL;
    if (i < M) g_best2[i] = ~0ULL;
    if (i < N / 2) {
        float x0 = pp[6*i],   y0 = pp[6*i+1], z0 = pp[6*i+2];
        float x1 = pp[6*i+3], y1 = pp[6*i+4], z1 = pp[6*i+5];
        g_pxy[i] = make_float4(x0, x1, y0, y1);
        g_pzw[i] = make_float4(z0, z1, x0*x0 + y0*y0 + z0*z0,
                                       x1*x1 + y1*y1 + z1*z1);
    }
    if (i < M / 2) {
        float x0 = gp[6*i],   y0 = gp[6*i+1], z0 = gp[6*i+2];
        float x1 = gp[6*i+3], y1 = gp[6*i+4], z1 = gp[6*i+5];
        g_gxy[i] = make_float4(x0, x1, y0, y1);
        g_gzw[i] = make_float4(z0, z1, x0*x0 + y0*y0 + z0*z0,
                                       x1*x1 + y1*y1 + z1*z1);
    }
}

// ---------------- main: both directions, pure-min tiles ----------------------
// score(q, c) = |c|^2 - 2 q.c  (identical chain to validated rounds)
// atomicMin payload = (fkey(min)<<32 | tileId): smallest score, then earliest
// tile -> the tile holding the global first occurrence.
__global__ __launch_bounds__(TPB) void nn_main(const float* __restrict__ pp,
                                               const float* __restrict__ gp) {
    __shared__ ulonglong2 sxy[PAIRS];
    __shared__ ulonglong2 szw[PAIRS];

    int b = blockIdx.x;
    const ulonglong2 *gxy, *gzw;
    const float* qp;
    unsigned long long* best;
    int bx, by;
    if (b < NB0) {               // dir 0: pred queries vs gt candidates
        bx = b % BX0; by = b / BX0;
        gxy = (const ulonglong2*)g_gxy; gzw = (const ulonglong2*)g_gzw;
        qp = pp; best = g_best1;
    } else {                     // dir 1: gt queries vs pred candidates
        b -= NB0;
        bx = b % BX1; by = b / BX1;
        gxy = (const ulonglong2*)g_pxy; gzw = (const ulonglong2*)g_pzw;
        qp = gp; best = g_best2;
    }

    const int pairbase = by * PAIRS;
    for (int t = threadIdx.x; t < PAIRS; t += TPB) {
        sxy[t] = gxy[pairbase + t];
        szw[t] = gzw[pairbase + t];
    }
    __syncthreads();

    int q[QPT];
    unsigned long long Qx[QPT], Qy[QPT], Qz[QPT];
#pragma unroll
    for (int k = 0; k < QPT; k++) {
        q[k]  = bx * QPB + k * TPB + threadIdx.x;
        Qx[k] = splat2(-2.0f * qp[3*q[k]]);
        Qy[k] = splat2(-2.0f * qp[3*q[k]+1]);
        Qz[k] = splat2(-2.0f * qp[3*q[k]+2]);
    }

    float bm0[QPT], bm1[QPT];
#pragma unroll
    for (int k = 0; k < QPT; k++) { bm0[k] = 3.4e38f; bm1[k] = 3.4e38f; }

#pragma unroll 8
    for (int t = 0; t < PAIRS; t++) {
        ulonglong2 a = sxy[t];
        ulonglong2 c = szw[t];
#pragma unroll
        for (int k = 0; k < QPT; k++) {
            unsigned long long s =
                ffma2(Qx[k], a.x, ffma2(Qy[k], a.y, ffma2(Qz[k], c.x, c.y)));
            float s0, s1; unpack2(s, s0, s1);
            bm0[k] = fminf(bm0[k], s0);
            bm1[k] = fminf(bm1[k], s1);
        }
    }

#pragma unroll
    for (int k = 0; k < QPT; k++) {
        float bm = fminf(bm0[k], bm1[k]);
        atomicMin(&best[q[k]],
                  ((unsigned long long)fkey(bm) << 32) | (unsigned)by);
    }
}

// ---------------- resolve + loss + final reduce (last-block) -----------------
// Rescans each query's winning tile with bit-identical arithmetic, takes the
// smallest exactly-equal index, accumulates normal dots, and the last block to
// finish performs the deterministic final reduction and writes the output.
__global__ __launch_bounds__(256) void resolve_loss(const float* __restrict__ pp,
                                                    const float* __restrict__ gp,
                                                    const float* __restrict__ pn,
                                                    const float* __restrict__ gn,
                                                    float* __restrict__ out,
                                                    int N, int M) {
    const int wid  = threadIdx.x >> 5;
    const int lane = threadIdx.x & 31;
    const int warp = blockIdx.x * 8 + wid;
    const int nw   = RLB * 8;
    float s1 = 0.f, s2 = 0.f;

    for (int w = warp; w < N + M; w += nw) {
        int dir = (w >= N);
        int q   = dir ? (w - N) : w;
        unsigned long long bk = dir ? g_best2[q] : g_best1[q];
        float bm = unfkey((unsigned)(bk >> 32));
        int tile = (int)(unsigned)bk;

        const ulonglong2* gxy = dir ? (const ulonglong2*)g_pxy
                                    : (const ulonglong2*)g_gxy;
        const ulonglong2* gzw = dir ? (const ulonglong2*)g_pzw
                                    : (const ulonglong2*)g_gzw;
        const float* qp = dir ? gp : pp;

        unsigned long long Qx = splat2(-2.0f * qp[3*q]);
        unsigned long long Qy = splat2(-2.0f * qp[3*q+1]);
        unsigned long long Qz = splat2(-2.0f * qp[3*q+2]);

        const int base = tile * PAIRS;
        int idx = 0x7FFFFFFF;
#pragma unroll
        for (int t = lane; t < PAIRS; t += 32) {
            ulonglong2 a = gxy[base + t];
            ulonglong2 c = gzw[base + t];
            unsigned long long s =
                ffma2(Qx, a.x, ffma2(Qy, a.y, ffma2(Qz, c.x, c.y)));
            float s0, sh; unpack2(s, s0, sh);
            if (sh == bm) idx = min(idx, 2*(base + t) + 1);
            if (s0 == bm) idx = min(idx, 2*(base + t));
        }
#pragma unroll
        for (int o = 16; o; o >>= 1)
            idx = min(idx, __shfl_xor_sync(0xFFFFFFFFu, idx, o));

        if (lane == 0) {
            const float* qn = dir ? gn : pn;   // query-side normals
            const float* cn = dir ? pn : gn;   // candidate-side normals
            float d = qn[3*q] * cn[3*idx] + qn[3*q+1] * cn[3*idx+1]
                    + qn[3*q+2] * cn[3*idx+2];
            if (dir) s2 += d; else s1 += d;
        }
    }

    __shared__ float sh1[8], sh2[8];
    if (lane == 0) { sh1[wid] = s1; sh2[wid] = s2; }
    __syncthreads();
    if (threadIdx.x == 0) {
        float a = 0.f, b = 0.f;
#pragma unroll
        for (int k = 0; k < 8; k++) { a += sh1[k]; b += sh2[k]; }
        g_partial[blockIdx.x]       = a;
        g_partial[RLB + blockIdx.x] = b;
    }

    // ---- last block performs the final deterministic reduction ----
    __shared__ bool amLast;
    __threadfence();
    if (threadIdx.x == 0)
        amLast = (atomicAdd(&g_done, 1u) == RLB - 1);
    __syncthreads();
    if (amLast) {
        __shared__ float sa[256], sb[256];
        int t = threadIdx.x;
        sa[t] = g_partial[t]       + g_partial[256 + t];
        sb[t] = g_partial[512 + t] + g_partial[768 + t];
        __syncthreads();
        for (int o = 128; o > 0; o >>= 1) {
            if (t < o) { sa[t] += sa[t + o]; sb[t] += sb[t + o]; }
            __syncthreads();
        }
        if (t == 0)
            out[0] = 2.0f - sa[0] / (float)N - sb[0] / (float)M;
    }
}

// ---------------- launch (3 nodes) -------------------------------------------
extern "C" void kernel_launch(void* const* d_in, const int* in_sizes, int n_in,
                              void* d_out, int out_size) {
    const float* pred_pts = (const float*)d_in[0];
    const float* pred_nrm = (const float*)d_in[1];
    const float* gt_pts   = (const float*)d_in[2];
    const float* gt_nrm   = (const float*)d_in[3];
    float* out = (float*)d_out;

    const int N = in_sizes[0] / 3;   // 8192
    const int M = in_sizes[2] / 3;   // 32768

    prep_kernel<<<(M + 255) / 256, 256>>>(pred_pts, gt_pts, N, M);
    nn_main<<<NB0 + NB1, TPB>>>(pred_pts, gt_pts);       // 2048 blocks
    resolve_loss<<<RLB, 256>>>(pred_pts, gt_pts, pred_nrm, gt_nrm, out, N, M);
}

// round 16
// speedup vs baseline: 1.1139x; 1.0977x over previous
#include <cuda_runtime.h>

#define TPB    128
#define QPT    4             // queries per thread
#define QPB    (TPB*QPT)     // 512 queries per block
#define PAIRS  256           // candidate pairs per tile (512 candidates)
#define GPAIRS 32            // pairs per granule (resolve unit: 1 pair/lane)
#define NGRP   (PAIRS/GPAIRS) // 8 granules per tile
#define BX0    16            // 8192/512   query-blocks dir0
#define BY0    64            // 32768/512  tiles dir0
#define BX1    64            // 32768/512  query-blocks dir1
#define BY1    16            // 8192/512   tiles dir1
#define NB0    (BX0*BY0)     // 1024
#define NB1    (BX1*BY1)     // 1024
#define RLB    512           // resolve_loss blocks

// ---------------- static scratch (no allocations) ----------------------------
__device__ float4             g_gxy[16384];   // gt  pairs: (x0,x1,y0,y1)
__device__ float4             g_gzw[16384];   // gt  pairs: (z0,z1,w0,w1)
__device__ float4             g_pxy[4096];    // pred pairs
__device__ float4             g_pzw[4096];
__device__ unsigned long long g_best1[8192];  // per pred: key | granule
__device__ unsigned long long g_best2[32768]; // per gt:   key | granule
__device__ float              g_partial[2*RLB];
__device__ unsigned           g_done;

// ---------------- packed f32x2 helpers ---------------------------------------
__device__ __forceinline__ unsigned long long splat2(float f) {
    unsigned long long r;
    asm("mov.b64 %0, {%1, %1};" : "=l"(r) : "f"(f));
    return r;
}
__device__ __forceinline__ unsigned long long ffma2(unsigned long long a,
                                                    unsigned long long b,
                                                    unsigned long long c) {
    unsigned long long d;
    asm("fma.rn.f32x2 %0, %1, %2, %3;" : "=l"(d) : "l"(a), "l"(b), "l"(c));
    return d;
}
__device__ __forceinline__ void unpack2(unsigned long long v, float& lo, float& hi) {
    asm("mov.b64 {%0, %1}, %2;" : "=f"(lo), "=f"(hi) : "l"(v));
}
// monotone float -> sortable unsigned, and exact inverse
__device__ __forceinline__ unsigned fkey(float f) {
    unsigned u = __float_as_uint(f);
    return u ^ ((unsigned)((int)u >> 31) | 0x80000000u);
}
__device__ __forceinline__ float unfkey(unsigned k) {
    return __uint_as_float((k & 0x80000000u) ? (k ^ 0x80000000u) : ~k);
}

// ---------------- prep: init winners + pack paired-SoA (one kernel) ----------
__global__ void prep_kernel(const float* __restrict__ pp,
                            const float* __restrict__ gp, int N, int M) {
    int i = blockIdx.x * blockDim.x + threadIdx.x;
    if (i == 0) g_done = 0;
    if (i < N) g_best1[i] = ~0ULL;
    if (i < M) g_best2[i] = ~0ULL;
    if (i < N / 2) {
        float x0 = pp[6*i],   y0 = pp[6*i+1], z0 = pp[6*i+2];
        float x1 = pp[6*i+3], y1 = pp[6*i+4], z1 = pp[6*i+5];
        g_pxy[i] = make_float4(x0, x1, y0, y1);
        g_pzw[i] = make_float4(z0, z1, x0*x0 + y0*y0 + z0*z0,
                                       x1*x1 + y1*y1 + z1*z1);
    }
    if (i < M / 2) {
        float x0 = gp[6*i],   y0 = gp[6*i+1], z0 = gp[6*i+2];
        float x1 = gp[6*i+3], y1 = gp[6*i+4], z1 = gp[6*i+5];
        g_gxy[i] = make_float4(x0, x1, y0, y1);
        g_gzw[i] = make_float4(z0, z1, x0*x0 + y0*y0 + z0*z0,
                                       x1*x1 + y1*y1 + z1*z1);
    }
}

// ---------------- main: both directions, min + winning-granule track ---------
// score(q, c) = |c|^2 - 2 q.c  (identical chain to validated rounds)
// atomicMin payload = (fkey(min)<<32 | granule): smallest score, then earliest
// granule -> the 64-candidate range holding the global first occurrence.
__global__ __launch_bounds__(TPB) void nn_main(const float* __restrict__ pp,
                                               const float* __restrict__ gp) {
    __shared__ ulonglong2 sxy[PAIRS];
    __shared__ ulonglong2 szw[PAIRS];

    int b = blockIdx.x;
    const ulonglong2 *gxy, *gzw;
    const float* qp;
    unsigned long long* best;
    int bx, by;
    if (b < NB0) {               // dir 0: pred queries vs gt candidates
        bx = b % BX0; by = b / BX0;
        gxy = (const ulonglong2*)g_gxy; gzw = (const ulonglong2*)g_gzw;
        qp = pp; best = g_best1;
    } else {                     // dir 1: gt queries vs pred candidates
        b -= NB0;
        bx = b % BX1; by = b / BX1;
        gxy = (const ulonglong2*)g_pxy; gzw = (const ulonglong2*)g_pzw;
        qp = gp; best = g_best2;
    }

    const int pairbase = by * PAIRS;
    for (int t = threadIdx.x; t < PAIRS; t += TPB) {
        sxy[t] = gxy[pairbase + t];
        szw[t] = gzw[pairbase + t];
    }
    __syncthreads();

    int q[QPT];
    unsigned long long Qx[QPT], Qy[QPT], Qz[QPT];
#pragma unroll
    for (int k = 0; k < QPT; k++) {
        q[k]  = bx * QPB + k * TPB + threadIdx.x;
        Qx[k] = splat2(-2.0f * qp[3*q[k]]);
        Qy[k] = splat2(-2.0f * qp[3*q[k]+1]);
        Qz[k] = splat2(-2.0f * qp[3*q[k]+2]);
    }

    float bm0[QPT], bm1[QPT], bm[QPT];
    int   bg[QPT];
#pragma unroll
    for (int k = 0; k < QPT; k++) {
        bm0[k] = 3.4e38f; bm1[k] = 3.4e38f; bm[k] = 3.4e38f; bg[k] = 0;
    }

    for (int g = 0; g < NGRP; g++) {
        float om[QPT];
#pragma unroll
        for (int k = 0; k < QPT; k++) om[k] = bm[k];
        const int t0 = g * GPAIRS;
#pragma unroll 8
        for (int t = t0; t < t0 + GPAIRS; t++) {
            ulonglong2 a = sxy[t];
            ulonglong2 c = szw[t];
#pragma unroll
            for (int k = 0; k < QPT; k++) {
                unsigned long long s =
                    ffma2(Qx[k], a.x, ffma2(Qy[k], a.y, ffma2(Qz[k], c.x, c.y)));
                float s0, s1; unpack2(s, s0, s1);
                bm0[k] = fminf(bm0[k], s0);
                bm1[k] = fminf(bm1[k], s1);
            }
        }
#pragma unroll
        for (int k = 0; k < QPT; k++) {
            bm[k] = fminf(bm0[k], bm1[k]);
            bg[k] = (bm[k] < om[k]) ? g : bg[k];   // strict drop => first group
        }
    }

#pragma unroll
    for (int k = 0; k < QPT; k++) {
        unsigned gran = (unsigned)(by * NGRP + bg[k]);
        atomicMin(&best[q[k]],
                  ((unsigned long long)fkey(bm[k]) << 32) | gran);
    }
}

// ---------------- resolve + loss + final reduce (last-block) -----------------
// One pair per lane over the 32-pair winning granule: recompute score with
// bit-identical arithmetic, smallest exactly-equal index wins, then accumulate
// the normal dot. Last block performs the deterministic final reduction.
__global__ __launch_bounds__(256) void resolve_loss(const float* __restrict__ pp,
                                                    const float* __restrict__ gp,
                                                    const float* __restrict__ pn,
                                                    const float* __restrict__ gn,
                                                    float* __restrict__ out,
                                                    int N, int M) {
    const int wid  = threadIdx.x >> 5;
    const int lane = threadIdx.x & 31;
    const int warp = blockIdx.x * 8 + wid;
    const int nw   = RLB * 8;
    float s1 = 0.f, s2 = 0.f;

    for (int w = warp; w < N + M; w += nw) {
        int dir = (w >= N);
        int q   = dir ? (w - N) : w;
        unsigned long long bk = dir ? g_best2[q] : g_best1[q];
        float bm = unfkey((unsigned)(bk >> 32));
        int basePair = (int)(unsigned)bk * GPAIRS;

        const ulonglong2* gxy = dir ? (const ulonglong2*)g_pxy
                                    : (const ulonglong2*)g_gxy;
        const ulonglong2* gzw = dir ? (const ulonglong2*)g_pzw
                                    : (const ulonglong2*)g_gzw;
        const float* qp = dir ? gp : pp;

        unsigned long long Qx = splat2(-2.0f * qp[3*q]);
        unsigned long long Qy = splat2(-2.0f * qp[3*q+1]);
        unsigned long long Qz = splat2(-2.0f * qp[3*q+2]);

        const int t = basePair + lane;           // one pair per lane
        ulonglong2 a = gxy[t];
        ulonglong2 c = gzw[t];
        unsigned long long s =
            ffma2(Qx, a.x, ffma2(Qy, a.y, ffma2(Qz, c.x, c.y)));
        float s0, sh; unpack2(s, s0, sh);
        int idx = 0x7FFFFFFF;
        if (sh == bm) idx = 2*t + 1;
        if (s0 == bm) idx = 2*t;
#pragma unroll
        for (int o = 16; o; o >>= 1)
            idx = min(idx, __shfl_xor_sync(0xFFFFFFFFu, idx, o));

        if (lane == 0) {
            const float* qn = dir ? gn : pn;   // query-side normals
            const float* cn = dir ? pn : gn;   // candidate-side normals
            float d = qn[3*q] * cn[3*idx] + qn[3*q+1] * cn[3*idx+1]
                    + qn[3*q+2] * cn[3*idx+2];
            if (dir) s2 += d; else s1 += d;
        }
    }

    __shared__ float sh1[8], sh2[8];
    if (lane == 0) { sh1[wid] = s1; sh2[wid] = s2; }
    __syncthreads();
    if (threadIdx.x == 0) {
        float a = 0.f, b = 0.f;
#pragma unroll
        for (int k = 0; k < 8; k++) { a += sh1[k]; b += sh2[k]; }
        g_partial[blockIdx.x]       = a;
        g_partial[RLB + blockIdx.x] = b;
    }

    // ---- last block performs the final deterministic reduction ----
    __shared__ bool amLast;
    __threadfence();
    if (threadIdx.x == 0)
        amLast = (atomicAdd(&g_done, 1u) == RLB - 1);
    __syncthreads();
    if (amLast) {
        __shared__ float sa[256], sb[256];
        int t = threadIdx.x;
        sa[t] = g_partial[t]       + g_partial[256 + t];
        sb[t] = g_partial[512 + t] + g_partial[768 + t];
        __syncthreads();
        for (int o = 128; o > 0; o >>= 1) {
            if (t < o) { sa[t] += sa[t + o]; sb[t] += sb[t + o]; }
            __syncthreads();
        }
        if (t == 0)
            out[0] = 2.0f - sa[0] / (float)N - sb[0] / (float)M;
    }
}

// ---------------- launch (3 nodes) -------------------------------------------
extern "C" void kernel_launch(void* const* d_in, const int* in_sizes, int n_in,
                              void* d_out, int out_size) {
    const float* pred_pts = (const float*)d_in[0];
    const float* pred_nrm = (const float*)d_in[1];
    const float* gt_pts   = (const float*)d_in[2];
    const float* gt_nrm   = (const float*)d_in[3];
    float* out = (float*)d_out;

    const int N = in_sizes[0] / 3;   // 8192
    const int M = in_sizes[2] / 3;   // 32768

    prep_kernel<<<(M + 255) / 256, 256>>>(pred_pts, gt_pts, N, M);
    nn_main<<<NB0 + NB1, TPB>>>(pred_pts, gt_pts);       // 2048 blocks
    resolve_loss<<<RLB, 256>>>(pred_pts, gt_pts, pred_nrm, gt_nrm, out, N, M);
}

// round 17
// speedup vs baseline: 1.1657x; 1.0465x over previous
#include <cuda_runtime.h>

#define TPB    128
#define QPT    4             // queries per thread
#define QPB    (TPB*QPT)     // 512 queries per block
#define PAIRS  128           // candidate pairs per tile (256 candidates)
#define GPAIRS 32            // pairs per granule (resolve unit: 1 pair/lane)
#define NGRP   (PAIRS/GPAIRS) // 4 granules per tile
#define BX0    16            // 8192/512   query-blocks dir0
#define BY0    128           // 32768/256  tiles dir0
#define BX1    64            // 32768/512  query-blocks dir1
#define BY1    32            // 8192/256   tiles dir1
#define NB0    (BX0*BY0)     // 2048
#define NB1    (BX1*BY1)     // 2048
#define RLB    1024          // resolve_loss blocks

// ---------------- static scratch (no allocations) ----------------------------
__device__ float4             g_gxy[16384];   // gt  pairs: (x0,x1,y0,y1)
__device__ float4             g_gzw[16384];   // gt  pairs: (z0,z1,w0,w1)
__device__ float4             g_pxy[4096];    // pred pairs
__device__ float4             g_pzw[4096];
__device__ unsigned long long g_best1[8192];  // per pred: key | granule
__device__ unsigned long long g_best2[32768]; // per gt:   key | granule
__device__ float              g_partial[2*RLB];
__device__ unsigned           g_done;

// ---------------- packed f32x2 helpers ---------------------------------------
__device__ __forceinline__ unsigned long long splat2(float f) {
    unsigned long long r;
    asm("mov.b64 %0, {%1, %1};" : "=l"(r) : "f"(f));
    return r;
}
__device__ __forceinline__ unsigned long long ffma2(unsigned long long a,
                                                    unsigned long long b,
                                                    unsigned long long c) {
    unsigned long long d;
    asm("fma.rn.f32x2 %0, %1, %2, %3;" : "=l"(d) : "l"(a), "l"(b), "l"(c));
    return d;
}
__device__ __forceinline__ void unpack2(unsigned long long v, float& lo, float& hi) {
    asm("mov.b64 {%0, %1}, %2;" : "=f"(lo), "=f"(hi) : "l"(v));
}
// monotone float -> sortable unsigned, and exact inverse
__device__ __forceinline__ unsigned fkey(float f) {
    unsigned u = __float_as_uint(f);
    return u ^ ((unsigned)((int)u >> 31) | 0x80000000u);
}
__device__ __forceinline__ float unfkey(unsigned k) {
    return __uint_as_float((k & 0x80000000u) ? (k ^ 0x80000000u) : ~k);
}

// ---------------- prep: init winners + pack paired-SoA (one kernel) ----------
__global__ void prep_kernel(const float* __restrict__ pp,
                            const float* __restrict__ gp, int N, int M) {
    int i = blockIdx.x * blockDim.x + threadIdx.x;
    if (i == 0) g_done = 0;
    if (i < N) g_best1[i] = ~0ULL;
    if (i < M) g_best2[i] = ~0ULL;
    if (i < N / 2) {
        float x0 = pp[6*i],   y0 = pp[6*i+1], z0 = pp[6*i+2];
        float x1 = pp[6*i+3], y1 = pp[6*i+4], z1 = pp[6*i+5];
        g_pxy[i] = make_float4(x0, x1, y0, y1);
        g_pzw[i] = make_float4(z0, z1, x0*x0 + y0*y0 + z0*z0,
                                       x1*x1 + y1*y1 + z1*z1);
    }
    if (i < M / 2) {
        float x0 = gp[6*i],   y0 = gp[6*i+1], z0 = gp[6*i+2];
        float x1 = gp[6*i+3], y1 = gp[6*i+4], z1 = gp[6*i+5];
        g_gxy[i] = make_float4(x0, x1, y0, y1);
        g_gzw[i] = make_float4(z0, z1, x0*x0 + y0*y0 + z0*z0,
                                       x1*x1 + y1*y1 + z1*z1);
    }
}

// ---------------- main: both directions, min + winning-granule track ---------
// score(q, c) = |c|^2 - 2 q.c  (identical chain to validated rounds)
// atomicMin payload = (fkey(min)<<32 | granule): smallest score, then earliest
// granule -> the 64-candidate range holding the global first occurrence.
__global__ __launch_bounds__(TPB) void nn_main(const float* __restrict__ pp,
                                               const float* __restrict__ gp) {
    __shared__ ulonglong2 sxy[PAIRS];
    __shared__ ulonglong2 szw[PAIRS];

    int b = blockIdx.x;
    const ulonglong2 *gxy, *gzw;
    const float* qp;
    unsigned long long* best;
    int bx, by;
    if (b < NB0) {               // dir 0: pred queries vs gt candidates
        bx = b % BX0; by = b / BX0;
        gxy = (const ulonglong2*)g_gxy; gzw = (const ulonglong2*)g_gzw;
        qp = pp; best = g_best1;
    } else {                     // dir 1: gt queries vs pred candidates
        b -= NB0;
        bx = b % BX1; by = b / BX1;
        gxy = (const ulonglong2*)g_pxy; gzw = (const ulonglong2*)g_pzw;
        qp = gp; best = g_best2;
    }

    const int pairbase = by * PAIRS;
    if (threadIdx.x < PAIRS) {
        sxy[threadIdx.x] = gxy[pairbase + threadIdx.x];
        szw[threadIdx.x] = gzw[pairbase + threadIdx.x];
    }
    __syncthreads();

    int q[QPT];
    unsigned long long Qx[QPT], Qy[QPT], Qz[QPT];
#pragma unroll
    for (int k = 0; k < QPT; k++) {
        q[k]  = bx * QPB + k * TPB + threadIdx.x;
        Qx[k] = splat2(-2.0f * qp[3*q[k]]);
        Qy[k] = splat2(-2.0f * qp[3*q[k]+1]);
        Qz[k] = splat2(-2.0f * qp[3*q[k]+2]);
    }

    float bm0[QPT], bm1[QPT], bm[QPT];
    int   bg[QPT];
#pragma unroll
    for (int k = 0; k < QPT; k++) {
        bm0[k] = 3.4e38f; bm1[k] = 3.4e38f; bm[k] = 3.4e38f; bg[k] = 0;
    }

    for (int g = 0; g < NGRP; g++) {
        float om[QPT];
#pragma unroll
        for (int k = 0; k < QPT; k++) om[k] = bm[k];
        const int t0 = g * GPAIRS;
#pragma unroll 8
        for (int t = t0; t < t0 + GPAIRS; t++) {
            ulonglong2 a = sxy[t];
            ulonglong2 c = szw[t];
#pragma unroll
            for (int k = 0; k < QPT; k++) {
                unsigned long long s =
                    ffma2(Qx[k], a.x, ffma2(Qy[k], a.y, ffma2(Qz[k], c.x, c.y)));
                float s0, s1; unpack2(s, s0, s1);
                bm0[k] = fminf(bm0[k], s0);
                bm1[k] = fminf(bm1[k], s1);
            }
        }
#pragma unroll
        for (int k = 0; k < QPT; k++) {
            bm[k] = fminf(bm0[k], bm1[k]);
            bg[k] = (bm[k] < om[k]) ? g : bg[k];   // strict drop => first group
        }
    }

#pragma unroll
    for (int k = 0; k < QPT; k++) {
        unsigned gran = (unsigned)(by * NGRP + bg[k]);
        atomicMin(&best[q[k]],
                  ((unsigned long long)fkey(bm[k]) << 32) | gran);
    }
}

// ---------------- resolve + loss + final reduce (last-block) -----------------
// One pair per lane over the 32-pair winning granule: recompute score with
// bit-identical arithmetic, smallest exactly-equal index wins, then accumulate
// the normal dot. Last block performs the deterministic final reduction.
__global__ __launch_bounds__(256) void resolve_loss(const float* __restrict__ pp,
                                                    const float* __restrict__ gp,
                                                    const float* __restrict__ pn,
                                                    const float* __restrict__ gn,
                                                    float* __restrict__ out,
                                                    int N, int M) {
    const int wid  = threadIdx.x >> 5;
    const int lane = threadIdx.x & 31;
    const int warp = blockIdx.x * 8 + wid;
    const int nw   = RLB * 8;
    float s1 = 0.f, s2 = 0.f;

    for (int w = warp; w < N + M; w += nw) {
        int dir = (w >= N);
        int q   = dir ? (w - N) : w;
        unsigned long long bk = dir ? g_best2[q] : g_best1[q];
        float bm = unfkey((unsigned)(bk >> 32));
        int basePair = (int)(unsigned)bk * GPAIRS;

        const ulonglong2* gxy = dir ? (const ulonglong2*)g_pxy
                                    : (const ulonglong2*)g_gxy;
        const ulonglong2* gzw = dir ? (const ulonglong2*)g_pzw
                                    : (const ulonglong2*)g_gzw;
        const float* qp = dir ? gp : pp;

        unsigned long long Qx = splat2(-2.0f * qp[3*q]);
        unsigned long long Qy = splat2(-2.0f * qp[3*q+1]);
        unsigned long long Qz = splat2(-2.0f * qp[3*q+2]);

        const int t = basePair + lane;           // one pair per lane
        ulonglong2 a = gxy[t];
        ulonglong2 c = gzw[t];
        unsigned long long s =
            ffma2(Qx, a.x, ffma2(Qy, a.y, ffma2(Qz, c.x, c.y)));
        float s0, sh; unpack2(s, s0, sh);
        int idx = 0x7FFFFFFF;
        if (sh == bm) idx = 2*t + 1;
        if (s0 == bm) idx = 2*t;
#pragma unroll
        for (int o = 16; o; o >>= 1)
            idx = min(idx, __shfl_xor_sync(0xFFFFFFFFu, idx, o));

        if (lane == 0) {
            const float* qn = dir ? gn : pn;   // query-side normals
            const float* cn = dir ? pn : gn;   // candidate-side normals
            float d = qn[3*q] * cn[3*idx] + qn[3*q+1] * cn[3*idx+1]
                    + qn[3*q+2] * cn[3*idx+2];
            if (dir) s2 += d; else s1 += d;
        }
    }

    __shared__ float sh1[8], sh2[8];
    if (lane == 0) { sh1[wid] = s1; sh2[wid] = s2; }
    __syncthreads();
    if (threadIdx.x == 0) {
        float a = 0.f, b = 0.f;
#pragma unroll
        for (int k = 0; k < 8; k++) { a += sh1[k]; b += sh2[k]; }
        g_partial[blockIdx.x]       = a;
        g_partial[RLB + blockIdx.x] = b;
    }

    // ---- last block performs the final deterministic reduction ----
    __shared__ bool amLast;
    __threadfence();
    if (threadIdx.x == 0)
        amLast = (atomicAdd(&g_done, 1u) == RLB - 1);
    __syncthreads();
    if (amLast) {
        __shared__ float sa[256], sb[256];
        int t = threadIdx.x;
        sa[t] = g_partial[t]        + g_partial[256 + t]
              + g_partial[512 + t]  + g_partial[768 + t];
        sb[t] = g_partial[1024 + t] + g_partial[1280 + t]
              + g_partial[1536 + t] + g_partial[1792 + t];
        __syncthreads();
        for (int o = 128; o > 0; o >>= 1) {
            if (t < o) { sa[t] += sa[t + o]; sb[t] += sb[t + o]; }
            __syncthreads();
        }
        if (t == 0)
            out[0] = 2.0f - sa[0] / (float)N - sb[0] / (float)M;
    }
}

// ---------------- launch (3 nodes) -------------------------------------------
extern "C" void kernel_launch(void* const* d_in, const int* in_sizes, int n_in,
                              void* d_out, int out_size) {
    const float* pred_pts = (const float*)d_in[0];
    const float* pred_nrm = (const float*)d_in[1];
    const float* gt_pts   = (const float*)d_in[2];
    const float* gt_nrm   = (const float*)d_in[3];
    float* out = (float*)d_out;

    const int N = in_sizes[0] / 3;   // 8192
    const int M = in_sizes[2] / 3;   // 32768

    prep_kernel<<<(M + 255) / 256, 256>>>(pred_pts, gt_pts, N, M);
    nn_main<<<NB0 + NB1, TPB>>>(pred_pts, gt_pts);       // 4096 blocks
    resolve_loss<<<RLB, 256>>>(pred_pts, gt_pts, pred_nrm, gt_nrm, out, N, M);
}